// round 2
// baseline (speedup 1.0000x reference)
#include <cuda_runtime.h>

#define N_NODES 50000
#define N_EDGES 800000
#define HID 256
#define OUTC 128
#define NEG_SLOPE 0.2f

// ---------------- scratch (device globals; no allocations allowed) ----------
__device__ float g_H[(size_t)N_NODES * HID];    // h_src buffer (both layers)
__device__ float g_X1[(size_t)N_NODES * HID];   // layer-1 output / agg buffer
__device__ float g_asrc[N_NODES];
__device__ float g_adst[N_NODES];
__device__ float g_max[N_NODES];
__device__ float g_sum[N_NODES];
__device__ float g_e[N_EDGES];
__device__ float g_v[2 * HID];                  // v_src | v_dst

// ---------------- small helpers --------------------------------------------
__device__ __forceinline__ void atomicMaxFloat(float* addr, float val) {
    if (val >= 0.0f) atomicMax((int*)addr, __float_as_int(val));
    else             atomicMin((unsigned int*)addr, __float_as_uint(val));
}

// v = W @ att  (W: [Cin, Cout] row-major, att: [Cout]) ; blockIdx.x: 0=src 1=dst
__global__ void compute_v_kernel(const float* __restrict__ W_src,
                                 const float* __restrict__ att_src,
                                 const float* __restrict__ W_dst,
                                 const float* __restrict__ att_dst,
                                 int Cin, int Cout) {
    int k = threadIdx.x;
    if (k >= Cin) return;
    const float* W   = blockIdx.x ? W_dst   : W_src;
    const float* att = blockIdx.x ? att_dst : att_src;
    float s = 0.0f;
    for (int j = 0; j < Cout; j++) s += W[(size_t)k * Cout + j] * att[j];
    g_v[blockIdx.x * HID + k] = s;
}

// a_src[n] = dot(X[n], v_src); a_dst[n] = dot(X[n], v_dst). One warp / node.
__global__ void compute_a_kernel(const float* __restrict__ Xin, int Cin) {
    int t = blockIdx.x * blockDim.x + threadIdx.x;
    int node = t >> 5, lane = t & 31;
    if (node >= N_NODES) return;
    const float* X = Xin ? Xin : g_X1;
    float s1 = 0.0f, s2 = 0.0f;
    for (int c = lane; c < Cin; c += 32) {
        float xv = X[(size_t)node * Cin + c];
        s1 += xv * g_v[c];
        s2 += xv * g_v[HID + c];
    }
    #pragma unroll
    for (int o = 16; o; o >>= 1) {
        s1 += __shfl_down_sync(0xFFFFFFFFu, s1, o);
        s2 += __shfl_down_sync(0xFFFFFFFFu, s2, o);
    }
    if (lane == 0) { g_asrc[node] = s1; g_adst[node] = s2; }
}

// ---------------- SGEMM: g_H = A @ B  (A: [M,K], B: [K,N]) -----------------
#define BM 64
#define BN 64
#define BK 16
__global__ void sgemm_kernel(const float* __restrict__ Ain,
                             const float* __restrict__ B,
                             int M, int K, int N) {
    __shared__ float As[BK][BM];
    __shared__ float Bs[BK][BN + 4];
    const float* A = Ain ? Ain : g_X1;

    int tx = threadIdx.x % 16;
    int ty = threadIdx.x / 16;
    int row0 = blockIdx.x * BM;
    int col0 = blockIdx.y * BN;

    float acc[4][4] = {};

    int lk = threadIdx.x % 16;   // A load: k index
    int lm = threadIdx.x / 16;   // A load: m base
    int bj = threadIdx.x % 64;   // B load: col
    int bk = threadIdx.x / 64;   // B load: k base

    for (int k0 = 0; k0 < K; k0 += BK) {
        #pragma unroll
        for (int r = 0; r < 4; r++) {
            int m = lm + r * 16;
            int grow = row0 + m;
            As[lk][m] = (grow < M) ? A[(size_t)grow * K + k0 + lk] : 0.0f;
        }
        #pragma unroll
        for (int r = 0; r < 4; r++) {
            int k = bk + r * 4;
            Bs[k][bj] = B[(size_t)(k0 + k) * N + col0 + bj];
        }
        __syncthreads();

        #pragma unroll
        for (int k = 0; k < BK; k++) {
            float a[4], b[4];
            #pragma unroll
            for (int i = 0; i < 4; i++) a[i] = As[k][ty * 4 + i];
            #pragma unroll
            for (int j = 0; j < 4; j++) b[j] = Bs[k][tx * 4 + j];
            #pragma unroll
            for (int i = 0; i < 4; i++)
                #pragma unroll
                for (int j = 0; j < 4; j++)
                    acc[i][j] = fmaf(a[i], b[j], acc[i][j]);
        }
        __syncthreads();
    }

    #pragma unroll
    for (int i = 0; i < 4; i++) {
        int row = row0 + ty * 4 + i;
        if (row >= M) continue;
        #pragma unroll
        for (int j = 0; j < 4; j++) {
            g_H[(size_t)row * N + col0 + tx * 4 + j] = acc[i][j];
        }
    }
}

// ---------------- softmax passes -------------------------------------------
__global__ void init_nodes_kernel() {
    int i = blockIdx.x * blockDim.x + threadIdx.x;
    if (i >= N_NODES) return;
    g_max[i] = -__int_as_float(0x7F800000);  // -inf
    g_sum[i] = 0.0f;
}

__global__ void edge_logits_kernel(const int* __restrict__ ei) {
    int i = blockIdx.x * blockDim.x + threadIdx.x;
    if (i >= N_EDGES) return;
    int s = ei[i];
    int d = ei[N_EDGES + i];
    float e = g_asrc[s] + g_adst[d];
    e = (e > 0.0f) ? e : NEG_SLOPE * e;
    g_e[i] = e;
    atomicMaxFloat(&g_max[d], e);
}

__global__ void edge_exp_kernel(const int* __restrict__ ei) {
    int i = blockIdx.x * blockDim.x + threadIdx.x;
    if (i >= N_EDGES) return;
    int d = ei[N_EDGES + i];
    float ex = __expf(g_e[i] - g_max[d]);
    g_e[i] = ex;
    atomicAdd(&g_sum[d], ex);
}

__global__ void inv_sum_kernel() {
    int i = blockIdx.x * blockDim.x + threadIdx.x;
    if (i >= N_NODES) return;
    g_sum[i] = 1.0f / (g_sum[i] + 1e-16f);
}

// ---------------- aggregation ----------------------------------------------
__global__ void zero_X1_kernel() {
    int i = blockIdx.x * blockDim.x + threadIdx.x;
    if (i < N_NODES * HID) g_X1[i] = 0.0f;
}

__global__ void init_out_kernel(float* __restrict__ out, const float* __restrict__ b) {
    int i = blockIdx.x * blockDim.x + threadIdx.x;
    if (i < N_NODES * OUTC) out[i] = b[i % OUTC];
}

// One warp per edge: out[dst] += alpha * g_H[src]
template <int C>
__global__ void scatter_kernel(const int* __restrict__ ei,
                               float* __restrict__ outp) {
    int warp = (blockIdx.x * blockDim.x + threadIdx.x) >> 5;
    int lane = threadIdx.x & 31;
    if (warp >= N_EDGES) return;
    int s = ei[warp];
    int d = ei[N_EDGES + warp];
    float alpha = g_e[warp] * g_sum[d];
    float* out = outp ? outp : g_X1;
    const float4* hp = reinterpret_cast<const float4*>(g_H + (size_t)s * C);
    float* ob = out + (size_t)d * C;
    #pragma unroll
    for (int i = lane; i < C / 4; i += 32) {
        float4 v = hp[i];
        atomicAdd(ob + 4 * i + 0, alpha * v.x);
        atomicAdd(ob + 4 * i + 1, alpha * v.y);
        atomicAdd(ob + 4 * i + 2, alpha * v.z);
        atomicAdd(ob + 4 * i + 3, alpha * v.w);
    }
}

__global__ void finalize_relu_kernel(const float* __restrict__ b) {
    int i = blockIdx.x * blockDim.x + threadIdx.x;
    if (i >= N_NODES * HID) return;
    g_X1[i] = fmaxf(g_X1[i] + b[i % HID], 0.0f);
}

// ---------------- launch ----------------------------------------------------
extern "C" void kernel_launch(void* const* d_in, const int* in_sizes, int n_in,
                              void* d_out, int out_size) {
    const float* x        = (const float*)d_in[0];
    const int*   ei       = (const int*)d_in[1];   // int32: JAX x64 disabled demotes int64
    const float* W1_src   = (const float*)d_in[2];
    const float* W1_dst   = (const float*)d_in[3];
    const float* att1_src = (const float*)d_in[4];
    const float* att1_dst = (const float*)d_in[5];
    const float* b1       = (const float*)d_in[6];
    const float* W2_src   = (const float*)d_in[7];
    const float* W2_dst   = (const float*)d_in[8];
    const float* att2_src = (const float*)d_in[9];
    const float* att2_dst = (const float*)d_in[10];
    const float* b2       = (const float*)d_in[11];
    float* out = (float*)d_out;

    const int nodeBlocks  = (N_NODES + 255) / 256;
    const int edgeBlocks  = (N_EDGES + 255) / 256;
    const int warpNodeBlk = (N_NODES * 32 + 255) / 256;
    const int warpEdgeBlk = (N_EDGES * 32 + 255) / 256;
    const int gemmRows    = (N_NODES + BM - 1) / BM;

    // ---------------- layer 1 (256 -> 256) ----------------
    compute_v_kernel<<<2, HID>>>(W1_src, att1_src, W1_dst, att1_dst, HID, HID);
    compute_a_kernel<<<warpNodeBlk, 256>>>(x, HID);
    sgemm_kernel<<<dim3(gemmRows, HID / BN), 256>>>(x, W1_src, N_NODES, HID, HID);
    init_nodes_kernel<<<nodeBlocks, 256>>>();
    edge_logits_kernel<<<edgeBlocks, 256>>>(ei);
    edge_exp_kernel<<<edgeBlocks, 256>>>(ei);
    inv_sum_kernel<<<nodeBlocks, 256>>>();
    zero_X1_kernel<<<(N_NODES * HID + 255) / 256, 256>>>();
    scatter_kernel<HID><<<warpEdgeBlk, 256>>>(ei, nullptr);
    finalize_relu_kernel<<<(N_NODES * HID + 255) / 256, 256>>>(b1);

    // ---------------- layer 2 (256 -> 128) ----------------
    compute_v_kernel<<<2, HID>>>(W2_src, att2_src, W2_dst, att2_dst, HID, OUTC);
    compute_a_kernel<<<warpNodeBlk, 256>>>(nullptr, HID);
    sgemm_kernel<<<dim3(gemmRows, OUTC / BN), 256>>>(nullptr, W2_src, N_NODES, HID, OUTC);
    init_nodes_kernel<<<nodeBlocks, 256>>>();
    edge_logits_kernel<<<edgeBlocks, 256>>>(ei);
    edge_exp_kernel<<<edgeBlocks, 256>>>(ei);
    inv_sum_kernel<<<nodeBlocks, 256>>>();
    init_out_kernel<<<(N_NODES * OUTC + 255) / 256, 256>>>(out, b2);
    scatter_kernel<OUTC><<<warpEdgeBlk, 256>>>(ei, out);
}

// round 3
// speedup vs baseline: 1.8306x; 1.8306x over previous
#include <cuda_runtime.h>

#define N_NODES 50000
#define N_EDGES 800000
#define HID 256
#define OUTC 128
#define NEG_SLOPE 0.2f

// ---------------- scratch (device globals; no allocations allowed) ----------
__device__ float g_H[(size_t)N_NODES * HID];    // h_src buffer (both layers)
__device__ float g_X1[(size_t)N_NODES * HID];   // layer-1 output / agg buffer
__device__ float g_asrc[N_NODES];
__device__ float g_adst[N_NODES];
__device__ float g_max[N_NODES];
__device__ float g_sum[N_NODES];
__device__ float g_e[N_EDGES];
__device__ float g_v[2 * HID];                  // v_src | v_dst

// ---------------- helpers ----------------------------------------------------
__device__ __forceinline__ void atomicMaxFloat(float* addr, float val) {
    if (val >= 0.0f) atomicMax((int*)addr, __float_as_int(val));
    else             atomicMin((unsigned int*)addr, __float_as_uint(val));
}

union F2U { float2 f; unsigned long long u; };

// packed fp32x2 FMA (SASS FFMA2) — 2x fp32 FMA throughput, full fp32 precision
__device__ __forceinline__ float2 fma2(float2 a, float2 b, float2 c) {
    F2U A, B, C, D;
    A.f = a; B.f = b; C.f = c;
    asm("fma.rn.f32x2 %0, %1, %2, %3;" : "=l"(D.u) : "l"(A.u), "l"(B.u), "l"(C.u));
    return D.f;
}

// v = W @ att  (W: [Cin, Cout] row-major, att: [Cout]) ; blockIdx.x: 0=src 1=dst
__global__ void compute_v_kernel(const float* __restrict__ W_src,
                                 const float* __restrict__ att_src,
                                 const float* __restrict__ W_dst,
                                 const float* __restrict__ att_dst,
                                 int Cin, int Cout) {
    int k = threadIdx.x;
    if (k >= Cin) return;
    const float* W   = blockIdx.x ? W_dst   : W_src;
    const float* att = blockIdx.x ? att_dst : att_src;
    float s = 0.0f;
    for (int j = 0; j < Cout; j++) s += W[(size_t)k * Cout + j] * att[j];
    g_v[blockIdx.x * HID + k] = s;
}

// a_src[n] = dot(X[n], v_src); a_dst[n] = dot(X[n], v_dst). One warp / node.
__global__ void compute_a_kernel(const float* __restrict__ Xin, int Cin) {
    int t = blockIdx.x * blockDim.x + threadIdx.x;
    int node = t >> 5, lane = t & 31;
    if (node >= N_NODES) return;
    const float* X = Xin ? Xin : g_X1;
    const float4* Xr = reinterpret_cast<const float4*>(X + (size_t)node * Cin);
    const float4* v1 = reinterpret_cast<const float4*>(g_v);
    const float4* v2 = reinterpret_cast<const float4*>(g_v + HID);
    float s1 = 0.0f, s2 = 0.0f;
    for (int c = lane; c < Cin / 4; c += 32) {
        float4 xv = Xr[c];
        float4 a = v1[c], b = v2[c];
        s1 += xv.x * a.x + xv.y * a.y + xv.z * a.z + xv.w * a.w;
        s2 += xv.x * b.x + xv.y * b.y + xv.z * b.z + xv.w * b.w;
    }
    #pragma unroll
    for (int o = 16; o; o >>= 1) {
        s1 += __shfl_down_sync(0xFFFFFFFFu, s1, o);
        s2 += __shfl_down_sync(0xFFFFFFFFu, s2, o);
    }
    if (lane == 0) { g_asrc[node] = s1; g_adst[node] = s2; }
}

// ---------------- SGEMM 128x128x16, 8x8 microtile, f32x2 FMA ----------------
#define TBM 128
#define TBN 128
#define TBK 16
#define APAD 8   // pad so float4 rows stay 16B-aligned (136*4B = 544B % 16 == 0)

__global__ __launch_bounds__(256, 2)
void sgemm128_kernel(const float* __restrict__ Ain,
                     const float* __restrict__ B,
                     int M, int K, int N) {
    const float* A = Ain ? Ain : g_X1;
    __shared__ float As[2][TBK][TBM + APAD];
    __shared__ float Bs[2][TBK][TBN];

    const int tid  = threadIdx.x;          // 256 threads
    const int tx   = tid & 15;             // 16 col-groups
    const int ty   = tid >> 4;             // 16 row-groups
    const int row0 = blockIdx.x * TBM;
    const int col0 = blockIdx.y * TBN;

    float2 acc[8][4];
    #pragma unroll
    for (int i = 0; i < 8; i++)
        #pragma unroll
        for (int j = 0; j < 4; j++) acc[i][j] = make_float2(0.0f, 0.0f);

    // A load: 512 float4 per tile (128 rows x 4 float4/row), 2 per thread
    // B load: 512 float4 per tile (16 k-rows x 32 float4/row), 2 per thread
    auto loadTile = [&](int k0, int buf) {
        #pragma unroll
        for (int r = 0; r < 2; r++) {
            int f    = tid + r * 256;
            int row  = f >> 2;
            int kk   = (f & 3) * 4;
            int grow = row0 + row;
            float4 v = make_float4(0.f, 0.f, 0.f, 0.f);
            if (grow < M) v = *reinterpret_cast<const float4*>(&A[(size_t)grow * K + k0 + kk]);
            As[buf][kk + 0][row] = v.x;
            As[buf][kk + 1][row] = v.y;
            As[buf][kk + 2][row] = v.z;
            As[buf][kk + 3][row] = v.w;
        }
        #pragma unroll
        for (int r = 0; r < 2; r++) {
            int f    = tid + r * 256;
            int krow = f >> 5;
            int col  = (f & 31) * 4;
            float4 v = *reinterpret_cast<const float4*>(&B[(size_t)(k0 + krow) * N + col0 + col]);
            *reinterpret_cast<float4*>(&Bs[buf][krow][col]) = v;
        }
    };

    loadTile(0, 0);
    __syncthreads();

    for (int k0 = 0; k0 < K; k0 += TBK) {
        int buf = (k0 / TBK) & 1;
        if (k0 + TBK < K) loadTile(k0 + TBK, buf ^ 1);

        #pragma unroll
        for (int k = 0; k < TBK; k++) {
            float4 a0 = *reinterpret_cast<const float4*>(&As[buf][k][ty * 8]);
            float4 a1 = *reinterpret_cast<const float4*>(&As[buf][k][ty * 8 + 4]);
            float4 b0 = *reinterpret_cast<const float4*>(&Bs[buf][k][tx * 8]);
            float4 b1 = *reinterpret_cast<const float4*>(&Bs[buf][k][tx * 8 + 4]);
            float2 bp[4] = { make_float2(b0.x, b0.y), make_float2(b0.z, b0.w),
                             make_float2(b1.x, b1.y), make_float2(b1.z, b1.w) };
            float av[8] = { a0.x, a0.y, a0.z, a0.w, a1.x, a1.y, a1.z, a1.w };
            #pragma unroll
            for (int i = 0; i < 8; i++) {
                float2 ad = make_float2(av[i], av[i]);
                #pragma unroll
                for (int j = 0; j < 4; j++) acc[i][j] = fma2(ad, bp[j], acc[i][j]);
            }
        }
        __syncthreads();
    }

    #pragma unroll
    for (int i = 0; i < 8; i++) {
        int row = row0 + ty * 8 + i;
        if (row >= M) continue;
        float* op = &g_H[(size_t)row * N + col0 + tx * 8];
        float4 o0 = make_float4(acc[i][0].x, acc[i][0].y, acc[i][1].x, acc[i][1].y);
        float4 o1 = make_float4(acc[i][2].x, acc[i][2].y, acc[i][3].x, acc[i][3].y);
        *reinterpret_cast<float4*>(op)     = o0;
        *reinterpret_cast<float4*>(op + 4) = o1;
    }
}

// ---------------- softmax passes -------------------------------------------
__global__ void init_nodes_kernel() {
    int i = blockIdx.x * blockDim.x + threadIdx.x;
    if (i >= N_NODES) return;
    g_max[i] = -__int_as_float(0x7F800000);  // -inf
    g_sum[i] = 0.0f;
}

__global__ void edge_logits_kernel(const int* __restrict__ ei) {
    int i = blockIdx.x * blockDim.x + threadIdx.x;
    if (i >= N_EDGES) return;
    int s = ei[i];
    int d = ei[N_EDGES + i];
    float e = g_asrc[s] + g_adst[d];
    e = (e > 0.0f) ? e : NEG_SLOPE * e;
    g_e[i] = e;
    atomicMaxFloat(&g_max[d], e);
}

__global__ void edge_exp_kernel(const int* __restrict__ ei) {
    int i = blockIdx.x * blockDim.x + threadIdx.x;
    if (i >= N_EDGES) return;
    int d = ei[N_EDGES + i];
    float ex = __expf(g_e[i] - g_max[d]);
    g_e[i] = ex;
    atomicAdd(&g_sum[d], ex);
}

__global__ void inv_sum_kernel() {
    int i = blockIdx.x * blockDim.x + threadIdx.x;
    if (i >= N_NODES) return;
    g_sum[i] = 1.0f / (g_sum[i] + 1e-16f);
}

// ---------------- aggregation ----------------------------------------------
__global__ void zero_X1_kernel() {
    int i = blockIdx.x * blockDim.x + threadIdx.x;
    if (i < N_NODES * HID) g_X1[i] = 0.0f;
}

__global__ void init_out_kernel(float* __restrict__ out, const float* __restrict__ b) {
    int i = blockIdx.x * blockDim.x + threadIdx.x;
    if (i < N_NODES * OUTC) out[i] = b[i % OUTC];
}

// One warp per edge: out[dst] += alpha * g_H[src], vectorized red.v4
template <int C>
__global__ void scatter_kernel(const int* __restrict__ ei,
                               float* __restrict__ outp) {
    int warp = (blockIdx.x * blockDim.x + threadIdx.x) >> 5;
    int lane = threadIdx.x & 31;
    if (warp >= N_EDGES) return;
    int s = ei[warp];
    int d = ei[N_EDGES + warp];
    float alpha = g_e[warp] * g_sum[d];
    float* out = outp ? outp : g_X1;
    const float4* hp = reinterpret_cast<const float4*>(g_H + (size_t)s * C);
    float4* ob = reinterpret_cast<float4*>(out + (size_t)d * C);
    #pragma unroll
    for (int i = lane; i < C / 4; i += 32) {
        float4 v = hp[i];
        asm volatile("red.global.add.v4.f32 [%0], {%1, %2, %3, %4};"
                     :: "l"(ob + i),
                        "f"(alpha * v.x), "f"(alpha * v.y),
                        "f"(alpha * v.z), "f"(alpha * v.w)
                     : "memory");
    }
}

__global__ void finalize_relu_kernel(const float* __restrict__ b) {
    int i = blockIdx.x * blockDim.x + threadIdx.x;
    if (i >= N_NODES * HID) return;
    g_X1[i] = fmaxf(g_X1[i] + b[i % HID], 0.0f);
}

// ---------------- launch ----------------------------------------------------
extern "C" void kernel_launch(void* const* d_in, const int* in_sizes, int n_in,
                              void* d_out, int out_size) {
    const float* x        = (const float*)d_in[0];
    const int*   ei       = (const int*)d_in[1];   // int32 (JAX x64 disabled)
    const float* W1_src   = (const float*)d_in[2];
    const float* W1_dst   = (const float*)d_in[3];
    const float* att1_src = (const float*)d_in[4];
    const float* att1_dst = (const float*)d_in[5];
    const float* b1       = (const float*)d_in[6];
    const float* W2_src   = (const float*)d_in[7];
    const float* W2_dst   = (const float*)d_in[8];
    const float* att2_src = (const float*)d_in[9];
    const float* att2_dst = (const float*)d_in[10];
    const float* b2       = (const float*)d_in[11];
    float* out = (float*)d_out;

    const int nodeBlocks  = (N_NODES + 255) / 256;
    const int edgeBlocks  = (N_EDGES + 255) / 256;
    const int warpNodeBlk = (N_NODES * 32 + 255) / 256;
    const int warpEdgeBlk = (N_EDGES * 32 + 255) / 256;
    const int gemmRows    = (N_NODES + TBM - 1) / TBM;

    // ---------------- layer 1 (256 -> 256) ----------------
    compute_v_kernel<<<2, HID>>>(W1_src, att1_src, W1_dst, att1_dst, HID, HID);
    compute_a_kernel<<<warpNodeBlk, 256>>>(x, HID);
    sgemm128_kernel<<<dim3(gemmRows, HID / TBN), 256>>>(x, W1_src, N_NODES, HID, HID);
    init_nodes_kernel<<<nodeBlocks, 256>>>();
    edge_logits_kernel<<<edgeBlocks, 256>>>(ei);
    edge_exp_kernel<<<edgeBlocks, 256>>>(ei);
    inv_sum_kernel<<<nodeBlocks, 256>>>();
    zero_X1_kernel<<<(N_NODES * HID + 255) / 256, 256>>>();
    scatter_kernel<HID><<<warpEdgeBlk, 256>>>(ei, nullptr);
    finalize_relu_kernel<<<(N_NODES * HID + 255) / 256, 256>>>(b1);

    // ---------------- layer 2 (256 -> 128) ----------------
    compute_v_kernel<<<2, HID>>>(W2_src, att2_src, W2_dst, att2_dst, HID, OUTC);
    compute_a_kernel<<<warpNodeBlk, 256>>>(nullptr, HID);
    sgemm128_kernel<<<dim3(gemmRows, OUTC / TBN), 256>>>(nullptr, W2_src, N_NODES, HID, OUTC);
    init_nodes_kernel<<<nodeBlocks, 256>>>();
    edge_logits_kernel<<<edgeBlocks, 256>>>(ei);
    edge_exp_kernel<<<edgeBlocks, 256>>>(ei);
    inv_sum_kernel<<<nodeBlocks, 256>>>();
    init_out_kernel<<<(N_NODES * OUTC + 255) / 256, 256>>>(out, b2);
    scatter_kernel<OUTC><<<warpEdgeBlk, 256>>>(ei, out);
}

// round 5
// speedup vs baseline: 2.2791x; 1.2450x over previous
#include <cuda_runtime.h>

#define N_NODES 50000
#define N_EDGES 800000
#define HID 256
#define OUTC 128
#define NEG_SLOPE 0.2f

// ---------------- scratch (device globals; no allocations allowed) ----------
__device__ float g_H[(size_t)N_NODES * HID];    // h_src buffer (both layers)
__device__ float g_X1[(size_t)N_NODES * HID];   // layer-1 output
__device__ float g_asrc[N_NODES];
__device__ float g_adst[N_NODES];
__device__ float g_v[2 * HID];                  // v_src | v_dst
// CSR (built once per launch; edge structure shared by both layers)
__device__ int g_deg[N_NODES];
__device__ int g_off[N_NODES + 1];
__device__ int g_pos[N_NODES];
__device__ int g_srcs[N_EDGES];                 // src node per dst-sorted slot

// ---------------- helpers ----------------------------------------------------
union F2U { float2 f; unsigned long long u; };

// packed fp32x2 FMA (SASS FFMA2) — 2x fp32 FMA throughput, full fp32 precision
__device__ __forceinline__ float2 fma2(float2 a, float2 b, float2 c) {
    F2U A, B, C, D;
    A.f = a; B.f = b; C.f = c;
    asm("fma.rn.f32x2 %0, %1, %2, %3;" : "=l"(D.u) : "l"(A.u), "l"(B.u), "l"(C.u));
    return D.f;
}

__device__ __forceinline__ float leaky(float e) {
    return (e > 0.0f) ? e : NEG_SLOPE * e;
}

// ---------------- CSR build --------------------------------------------------
__global__ void zero_deg_kernel() {
    int i = blockIdx.x * blockDim.x + threadIdx.x;
    if (i < N_NODES) g_deg[i] = 0;
}

__global__ void hist_kernel(const int* __restrict__ ei) {
    int i = blockIdx.x * blockDim.x + threadIdx.x;
    if (i >= N_EDGES) return;
    atomicAdd(&g_deg[ei[N_EDGES + i]], 1);
}

// single-block exclusive scan over N_NODES degrees
__global__ void scan_kernel() {
    __shared__ int partial[1024];
    const int t = threadIdx.x;
    const int CH = (N_NODES + 1023) / 1024;
    int b = t * CH;
    int e = b + CH; if (e > N_NODES) e = N_NODES;
    int s = 0;
    for (int i = b; i < e; i++) s += g_deg[i];
    partial[t] = s;
    __syncthreads();
    for (int off = 1; off < 1024; off <<= 1) {
        int v = (t >= off) ? partial[t - off] : 0;
        __syncthreads();
        partial[t] += v;
        __syncthreads();
    }
    int run = (t > 0) ? partial[t - 1] : 0;
    for (int i = b; i < e; i++) {
        int d = g_deg[i];
        g_off[i] = run;
        g_pos[i] = run;
        run += d;
    }
    if (t == 1023) g_off[N_NODES] = partial[1023];
}

__global__ void fill_kernel(const int* __restrict__ ei) {
    int i = blockIdx.x * blockDim.x + threadIdx.x;
    if (i >= N_EDGES) return;
    int d = ei[N_EDGES + i];
    int slot = atomicAdd(&g_pos[d], 1);
    g_srcs[slot] = ei[i];
}

// v = W @ att  (W: [Cin, Cout] row-major) ; blockIdx.x: 0=src 1=dst
__global__ void compute_v_kernel(const float* __restrict__ W_src,
                                 const float* __restrict__ att_src,
                                 const float* __restrict__ W_dst,
                                 const float* __restrict__ att_dst,
                                 int Cin, int Cout) {
    int k = threadIdx.x;
    if (k >= Cin) return;
    const float* W   = blockIdx.x ? W_dst   : W_src;
    const float* att = blockIdx.x ? att_dst : att_src;
    float s = 0.0f;
    for (int j = 0; j < Cout; j++) s += W[(size_t)k * Cout + j] * att[j];
    g_v[blockIdx.x * HID + k] = s;
}

// a_src[n] = dot(X[n], v_src); a_dst[n] = dot(X[n], v_dst). One warp / node.
__global__ void compute_a_kernel(const float* __restrict__ Xin, int Cin) {
    int t = blockIdx.x * blockDim.x + threadIdx.x;
    int node = t >> 5, lane = t & 31;
    if (node >= N_NODES) return;
    const float* X = Xin ? Xin : g_X1;
    const float4* Xr = reinterpret_cast<const float4*>(X + (size_t)node * Cin);
    const float4* v1 = reinterpret_cast<const float4*>(g_v);
    const float4* v2 = reinterpret_cast<const float4*>(g_v + HID);
    float s1 = 0.0f, s2 = 0.0f;
    for (int c = lane; c < Cin / 4; c += 32) {
        float4 xv = Xr[c];
        float4 a = v1[c], b = v2[c];
        s1 += xv.x * a.x + xv.y * a.y + xv.z * a.z + xv.w * a.w;
        s2 += xv.x * b.x + xv.y * b.y + xv.z * b.z + xv.w * b.w;
    }
    #pragma unroll
    for (int o = 16; o; o >>= 1) {
        s1 += __shfl_down_sync(0xFFFFFFFFu, s1, o);
        s2 += __shfl_down_sync(0xFFFFFFFFu, s2, o);
    }
    if (lane == 0) { g_asrc[node] = s1; g_adst[node] = s2; }
}

// ---------------- SGEMM 128x128x16, 8x8 microtile, f32x2 FMA ----------------
#define TBM 128
#define TBN 128
#define TBK 16
#define APAD 8

__global__ __launch_bounds__(256, 2)
void sgemm128_kernel(const float* __restrict__ Ain,
                     const float* __restrict__ B,
                     int M, int K, int N) {
    const float* A = Ain ? Ain : g_X1;
    __shared__ float As[2][TBK][TBM + APAD];
    __shared__ float Bs[2][TBK][TBN];

    const int tid  = threadIdx.x;
    const int tx   = tid & 15;
    const int ty   = tid >> 4;
    const int row0 = blockIdx.x * TBM;
    const int col0 = blockIdx.y * TBN;

    float2 acc[8][4];
    #pragma unroll
    for (int i = 0; i < 8; i++)
        #pragma unroll
        for (int j = 0; j < 4; j++) acc[i][j] = make_float2(0.0f, 0.0f);

    auto loadTile = [&](int k0, int buf) {
        #pragma unroll
        for (int r = 0; r < 2; r++) {
            int f    = tid + r * 256;
            int row  = f >> 2;
            int kk   = (f & 3) * 4;
            int grow = row0 + row;
            float4 v = make_float4(0.f, 0.f, 0.f, 0.f);
            if (grow < M) v = *reinterpret_cast<const float4*>(&A[(size_t)grow * K + k0 + kk]);
            As[buf][kk + 0][row] = v.x;
            As[buf][kk + 1][row] = v.y;
            As[buf][kk + 2][row] = v.z;
            As[buf][kk + 3][row] = v.w;
        }
        #pragma unroll
        for (int r = 0; r < 2; r++) {
            int f    = tid + r * 256;
            int krow = f >> 5;
            int col  = (f & 31) * 4;
            float4 v = *reinterpret_cast<const float4*>(&B[(size_t)(k0 + krow) * N + col0 + col]);
            *reinterpret_cast<float4*>(&Bs[buf][krow][col]) = v;
        }
    };

    loadTile(0, 0);
    __syncthreads();

    for (int k0 = 0; k0 < K; k0 += TBK) {
        int buf = (k0 / TBK) & 1;
        if (k0 + TBK < K) loadTile(k0 + TBK, buf ^ 1);

        #pragma unroll
        for (int k = 0; k < TBK; k++) {
            float4 a0 = *reinterpret_cast<const float4*>(&As[buf][k][ty * 8]);
            float4 a1 = *reinterpret_cast<const float4*>(&As[buf][k][ty * 8 + 4]);
            float4 b0 = *reinterpret_cast<const float4*>(&Bs[buf][k][tx * 8]);
            float4 b1 = *reinterpret_cast<const float4*>(&Bs[buf][k][tx * 8 + 4]);
            float2 bp[4] = { make_float2(b0.x, b0.y), make_float2(b0.z, b0.w),
                             make_float2(b1.x, b1.y), make_float2(b1.z, b1.w) };
            float av[8] = { a0.x, a0.y, a0.z, a0.w, a1.x, a1.y, a1.z, a1.w };
            #pragma unroll
            for (int i = 0; i < 8; i++) {
                float2 ad = make_float2(av[i], av[i]);
                #pragma unroll
                for (int j = 0; j < 4; j++) acc[i][j] = fma2(ad, bp[j], acc[i][j]);
            }
        }
        __syncthreads();
    }

    #pragma unroll
    for (int i = 0; i < 8; i++) {
        int row = row0 + ty * 8 + i;
        if (row >= M) continue;
        float* op = &g_H[(size_t)row * N + col0 + tx * 8];
        float4 o0 = make_float4(acc[i][0].x, acc[i][0].y, acc[i][1].x, acc[i][1].y);
        float4 o1 = make_float4(acc[i][2].x, acc[i][2].y, acc[i][3].x, acc[i][3].y);
        *reinterpret_cast<float4*>(op)     = o0;
        *reinterpret_cast<float4*>(op + 4) = o1;
    }
}

// ---------------- fused softmax + aggregation (one warp per dst node) -------
// out[node] = sum_e alpha_e * g_H[src_e] + bias   (optional ReLU)
// outp == nullptr means "write to g_X1" (device-side resolution; a __device__
// symbol must never be passed as a host-side kernel argument).
template <int C, bool RELU>
__global__ void agg_kernel(float* __restrict__ outp, const float* __restrict__ bias) {
    int node = (blockIdx.x * blockDim.x + threadIdx.x) >> 5;
    int lane = threadIdx.x & 31;
    if (node >= N_NODES) return;
    float* out = outp ? outp : g_X1;
    const int beg = g_off[node];
    const int end = g_off[node + 1];
    const float adst = g_adst[node];

    // pass 1: warp max of leaky logits
    float m = -__int_as_float(0x7F800000);
    for (int j = beg + lane; j < end; j += 32)
        m = fmaxf(m, leaky(g_asrc[g_srcs[j]] + adst));
    #pragma unroll
    for (int o = 16; o; o >>= 1) m = fmaxf(m, __shfl_xor_sync(0xFFFFFFFFu, m, o));

    // pass 2: warp sum of exp
    float s = 0.0f;
    for (int j = beg + lane; j < end; j += 32)
        s += __expf(leaky(g_asrc[g_srcs[j]] + adst) - m);
    #pragma unroll
    for (int o = 16; o; o >>= 1) s += __shfl_xor_sync(0xFFFFFFFFu, s, o);
    const float inv = 1.0f / (s + 1e-16f);

    // pass 3: sequential edge loop, coalesced float4 row gather, register acc
    float4 acc0 = make_float4(0.f, 0.f, 0.f, 0.f);
    float4 acc1 = make_float4(0.f, 0.f, 0.f, 0.f);
    for (int j = beg; j < end; j++) {
        int src = g_srcs[j];                         // warp-broadcast
        float alpha = __expf(leaky(g_asrc[src] + adst) - m) * inv;
        const float4* hp = reinterpret_cast<const float4*>(g_H + (size_t)src * C);
        float4 v0 = hp[lane];
        acc0.x += alpha * v0.x; acc0.y += alpha * v0.y;
        acc0.z += alpha * v0.z; acc0.w += alpha * v0.w;
        if (C == 256) {
            float4 v1 = hp[32 + lane];
            acc1.x += alpha * v1.x; acc1.y += alpha * v1.y;
            acc1.z += alpha * v1.z; acc1.w += alpha * v1.w;
        }
    }

    const float4* bp = reinterpret_cast<const float4*>(bias);
    float4 b0 = bp[lane];
    acc0.x += b0.x; acc0.y += b0.y; acc0.z += b0.z; acc0.w += b0.w;
    if (RELU) {
        acc0.x = fmaxf(acc0.x, 0.f); acc0.y = fmaxf(acc0.y, 0.f);
        acc0.z = fmaxf(acc0.z, 0.f); acc0.w = fmaxf(acc0.w, 0.f);
    }
    float4* op = reinterpret_cast<float4*>(out + (size_t)node * C);
    op[lane] = acc0;
    if (C == 256) {
        float4 b1 = bp[32 + lane];
        acc1.x += b1.x; acc1.y += b1.y; acc1.z += b1.z; acc1.w += b1.w;
        if (RELU) {
            acc1.x = fmaxf(acc1.x, 0.f); acc1.y = fmaxf(acc1.y, 0.f);
            acc1.z = fmaxf(acc1.z, 0.f); acc1.w = fmaxf(acc1.w, 0.f);
        }
        op[32 + lane] = acc1;
    }
}

// ---------------- launch ----------------------------------------------------
extern "C" void kernel_launch(void* const* d_in, const int* in_sizes, int n_in,
                              void* d_out, int out_size) {
    const float* x        = (const float*)d_in[0];
    const int*   ei       = (const int*)d_in[1];   // int32 (JAX x64 disabled)
    const float* W1_src   = (const float*)d_in[2];
    const float* W1_dst   = (const float*)d_in[3];
    const float* att1_src = (const float*)d_in[4];
    const float* att1_dst = (const float*)d_in[5];
    const float* b1       = (const float*)d_in[6];
    const float* W2_src   = (const float*)d_in[7];
    const float* W2_dst   = (const float*)d_in[8];
    const float* att2_src = (const float*)d_in[9];
    const float* att2_dst = (const float*)d_in[10];
    const float* b2       = (const float*)d_in[11];
    float* out = (float*)d_out;

    const int nodeBlocks  = (N_NODES + 255) / 256;
    const int edgeBlocks  = (N_EDGES + 255) / 256;
    const int warpNodeBlk = (N_NODES * 32 + 255) / 256;
    const int gemmRows    = (N_NODES + TBM - 1) / TBM;

    // CSR build (shared by both layers)
    zero_deg_kernel<<<nodeBlocks, 256>>>();
    hist_kernel<<<edgeBlocks, 256>>>(ei);
    scan_kernel<<<1, 1024>>>();
    fill_kernel<<<edgeBlocks, 256>>>(ei);

    // ---------------- layer 1 (256 -> 256) ----------------
    compute_v_kernel<<<2, HID>>>(W1_src, att1_src, W1_dst, att1_dst, HID, HID);
    compute_a_kernel<<<warpNodeBlk, 256>>>(x, HID);
    sgemm128_kernel<<<dim3(gemmRows, HID / TBN), 256>>>(x, W1_src, N_NODES, HID, HID);
    agg_kernel<HID, true><<<warpNodeBlk, 256>>>(nullptr, b1);

    // ---------------- layer 2 (256 -> 128) ----------------
    compute_v_kernel<<<2, HID>>>(W2_src, att2_src, W2_dst, att2_dst, HID, OUTC);
    compute_a_kernel<<<warpNodeBlk, 256>>>(nullptr, HID);
    sgemm128_kernel<<<dim3(gemmRows, OUTC / TBN), 256>>>(nullptr, W2_src, N_NODES, HID, OUTC);
    agg_kernel<OUTC, false><<<warpNodeBlk, 256>>>(out, b2);
}

// round 7
// speedup vs baseline: 2.4527x; 1.0761x over previous
#include <cuda_runtime.h>
#include <cuda_bf16.h>
#include <mma.h>
#include <cstdint>

using namespace nvcuda;

#define N_NODES 50000
#define N_PAD   50048            // padded row count so full-tile stores stay in-bounds
#define N_EDGES 800000
#define HID 256
#define OUTC 128
#define NEG_SLOPE 0.2f

// ---------------- scratch (device globals; no allocations allowed) ----------
__device__ float g_H[(size_t)N_PAD * HID];      // h_src buffer (both layers)
__device__ float g_X1[(size_t)N_PAD * HID];     // layer-1 output
__device__ float g_asrc[N_NODES];
__device__ float g_adst[N_NODES];
__device__ float g_v[2 * HID];                  // v_src | v_dst
__device__ __nv_bfloat16 g_Bh[256 * 256];       // W^T hi (bf16, [N][K] K-major)
__device__ __nv_bfloat16 g_Bl[256 * 256];       // W^T lo
// CSR (built once per launch; edge structure shared by both layers)
__device__ int g_deg[N_NODES];
__device__ int g_off[N_NODES + 1];
__device__ int g_pos[N_NODES];
__device__ int g_srcs[N_EDGES];                 // src node per dst-sorted slot

__device__ __forceinline__ float leaky(float e) {
    return (e > 0.0f) ? e : NEG_SLOPE * e;
}

// ---------------- CSR build --------------------------------------------------
__global__ void zero_deg_kernel() {
    int i = blockIdx.x * blockDim.x + threadIdx.x;
    if (i < N_NODES) g_deg[i] = 0;
}

__global__ void hist_kernel(const int* __restrict__ ei) {
    int i = blockIdx.x * blockDim.x + threadIdx.x;
    if (i >= N_EDGES) return;
    atomicAdd(&g_deg[ei[N_EDGES + i]], 1);
}

__global__ void scan_kernel() {
    __shared__ int partial[1024];
    const int t = threadIdx.x;
    const int CH = (N_NODES + 1023) / 1024;
    int b = t * CH;
    int e = b + CH; if (e > N_NODES) e = N_NODES;
    int s = 0;
    for (int i = b; i < e; i++) s += g_deg[i];
    partial[t] = s;
    __syncthreads();
    for (int off = 1; off < 1024; off <<= 1) {
        int v = (t >= off) ? partial[t - off] : 0;
        __syncthreads();
        partial[t] += v;
        __syncthreads();
    }
    int run = (t > 0) ? partial[t - 1] : 0;
    for (int i = b; i < e; i++) {
        int d = g_deg[i];
        g_off[i] = run;
        g_pos[i] = run;
        run += d;
    }
    if (t == 1023) g_off[N_NODES] = partial[1023];
}

__global__ void fill_kernel(const int* __restrict__ ei) {
    int i = blockIdx.x * blockDim.x + threadIdx.x;
    if (i >= N_EDGES) return;
    int d = ei[N_EDGES + i];
    int slot = atomicAdd(&g_pos[d], 1);
    g_srcs[slot] = ei[i];
}

// ---------------- small dense helpers ----------------------------------------
__global__ void compute_v_kernel(const float* __restrict__ W_src,
                                 const float* __restrict__ att_src,
                                 const float* __restrict__ W_dst,
                                 const float* __restrict__ att_dst,
                                 int Cin, int Cout) {
    int k = threadIdx.x;
    if (k >= Cin) return;
    const float* W   = blockIdx.x ? W_dst   : W_src;
    const float* att = blockIdx.x ? att_dst : att_src;
    float s = 0.0f;
    for (int j = 0; j < Cout; j++) s += W[(size_t)k * Cout + j] * att[j];
    g_v[blockIdx.x * HID + k] = s;
}

__global__ void compute_a_kernel(const float* __restrict__ Xin, int Cin) {
    int t = blockIdx.x * blockDim.x + threadIdx.x;
    int node = t >> 5, lane = t & 31;
    if (node >= N_NODES) return;
    const float* X = Xin ? Xin : g_X1;
    const float4* Xr = reinterpret_cast<const float4*>(X + (size_t)node * Cin);
    const float4* v1 = reinterpret_cast<const float4*>(g_v);
    const float4* v2 = reinterpret_cast<const float4*>(g_v + HID);
    float s1 = 0.0f, s2 = 0.0f;
    for (int c = lane; c < Cin / 4; c += 32) {
        float4 xv = Xr[c];
        float4 a = v1[c], b = v2[c];
        s1 += xv.x * a.x + xv.y * a.y + xv.z * a.z + xv.w * a.w;
        s2 += xv.x * b.x + xv.y * b.y + xv.z * b.z + xv.w * b.w;
    }
    #pragma unroll
    for (int o = 16; o; o >>= 1) {
        s1 += __shfl_down_sync(0xFFFFFFFFu, s1, o);
        s2 += __shfl_down_sync(0xFFFFFFFFu, s2, o);
    }
    if (lane == 0) { g_asrc[node] = s1; g_adst[node] = s2; }
}

// W [K=256, Cout] fp32 -> g_Bh/g_Bl [Cout][256] bf16 hi/lo (transposed, K-major)
__global__ void convert_W_kernel(const float* __restrict__ W, int Cout) {
    int idx = blockIdx.x * blockDim.x + threadIdx.x;   // n*256 + k
    if (idx >= 256 * Cout) return;
    int n = idx >> 8, k = idx & 255;
    float w = W[(size_t)k * Cout + n];
    __nv_bfloat16 wh = __float2bfloat16(w);
    g_Bh[idx] = wh;
    g_Bl[idx] = __float2bfloat16(w - __bfloat162float(wh));
}

// ---------------- WMMA bf16x3 GEMM: g_H = A(fp32) @ W ------------------------
// 128x128 block tile, 8 warps in 4(m) x 2(n), warp tile 32x64.
// D = Ah*Bh + Ah*Bl + Al*Bh  (fp32 accumulate) — bf16x3 precision split.
#define LDA 72                                  // smem pitch (bf16 elems)
#define SM_MAT (128 * LDA)                      // elems per staged matrix
#define SM_BYTES (4 * SM_MAT * 2)               // 73728 bytes dynamic smem

__global__ __launch_bounds__(256, 1)
void wmma_gemm_kernel(const float* __restrict__ Ain, int M, int Ntot) {
    extern __shared__ __nv_bfloat16 sm[];
    __nv_bfloat16* Ah = sm;                     // [128][LDA] row-major (m, k)
    __nv_bfloat16* Al = Ah + SM_MAT;
    __nv_bfloat16* Bh = Al + SM_MAT;            // [128][LDA] (n, k) = col-major B
    __nv_bfloat16* Bl = Bh + SM_MAT;

    const float* A = Ain ? Ain : g_X1;
    const int tid  = threadIdx.x;
    const int wid  = tid >> 5;
    const int wm   = wid & 3;                   // 0..3 -> 32-row group
    const int wn   = wid >> 2;                  // 0..1 -> 64-col group
    const int row0 = blockIdx.x * 128;
    const int col0 = blockIdx.y * 128;

    wmma::fragment<wmma::accumulator, 16, 16, 16, float> acc[2][4];
    #pragma unroll
    for (int i = 0; i < 2; i++)
        #pragma unroll
        for (int j = 0; j < 4; j++) wmma::fill_fragment(acc[i][j], 0.0f);

    const uint32_t* BhG = reinterpret_cast<const uint32_t*>(g_Bh);
    const uint32_t* BlG = reinterpret_cast<const uint32_t*>(g_Bl);

    for (int c = 0; c < 4; c++) {
        const int k0 = c * 64;

        // stage A chunk [128 m][64 k]: fp32 -> bf16 hi/lo
        #pragma unroll 8
        for (int p = tid; p < 8192; p += 256) {
            int r = p >> 6, col = p & 63;
            int grow = row0 + r;
            float a = (grow < M) ? A[(size_t)grow * 256 + k0 + col] : 0.0f;
            __nv_bfloat16 ah = __float2bfloat16(a);
            Ah[r * LDA + col] = ah;
            Al[r * LDA + col] = __float2bfloat16(a - __bfloat162float(ah));
        }
        // stage B chunk [128 n][64 k] from pre-split globals (u32 granules)
        #pragma unroll 4
        for (int p = tid; p < 4096; p += 256) {
            int n = p >> 5, kp = p & 31;
            size_t gsrc = ((size_t)(col0 + n) * 256 + k0) / 2 + kp;
            *reinterpret_cast<uint32_t*>(&Bh[n * LDA + kp * 2]) = BhG[gsrc];
            *reinterpret_cast<uint32_t*>(&Bl[n * LDA + kp * 2]) = BlG[gsrc];
        }
        __syncthreads();

        #pragma unroll
        for (int kk = 0; kk < 4; kk++) {
            const int ks = kk * 16;
            wmma::fragment<wmma::matrix_b, 16, 16, 16, __nv_bfloat16, wmma::col_major> bh[4], bl[4];
            #pragma unroll
            for (int j = 0; j < 4; j++) {
                const __nv_bfloat16* bp = &Bh[(wn * 64 + j * 16) * LDA + ks];
                const __nv_bfloat16* lp = &Bl[(wn * 64 + j * 16) * LDA + ks];
                wmma::load_matrix_sync(bh[j], bp, LDA);
                wmma::load_matrix_sync(bl[j], lp, LDA);
            }
            #pragma unroll
            for (int i = 0; i < 2; i++) {
                wmma::fragment<wmma::matrix_a, 16, 16, 16, __nv_bfloat16, wmma::row_major> ah, al;
                wmma::load_matrix_sync(ah, &Ah[(wm * 32 + i * 16) * LDA + ks], LDA);
                wmma::load_matrix_sync(al, &Al[(wm * 32 + i * 16) * LDA + ks], LDA);
                #pragma unroll
                for (int j = 0; j < 4; j++) {
                    wmma::mma_sync(acc[i][j], ah, bh[j], acc[i][j]);
                    wmma::mma_sync(acc[i][j], ah, bl[j], acc[i][j]);
                    wmma::mma_sync(acc[i][j], al, bh[j], acc[i][j]);
                }
            }
        }
        __syncthreads();
    }

    // epilogue: store warp tiles to g_H (rows padded to N_PAD -> always in-bounds)
    #pragma unroll
    for (int i = 0; i < 2; i++) {
        int grow = row0 + wm * 32 + i * 16;
        #pragma unroll
        for (int j = 0; j < 4; j++) {
            float* op = &g_H[(size_t)grow * Ntot + col0 + wn * 64 + j * 16];
            wmma::store_matrix_sync(op, acc[i][j], Ntot, wmma::mem_row_major);
        }
    }
}

// ---------------- fused softmax + aggregation (WPN warps per dst node) ------
template <int C, bool RELU, int WPN>
__global__ void agg_kernel(float* __restrict__ outp, const float* __restrict__ bias) {
    int gw   = (blockIdx.x * blockDim.x + threadIdx.x) >> 5;
    int lane = threadIdx.x & 31;
    int node = gw / WPN;
    int part = gw % WPN;
    if (node >= N_NODES) return;
    float* out = outp ? outp : g_X1;
    const int beg = g_off[node];
    const int end = g_off[node + 1];
    const float adst = g_adst[node];

    // pass 1: warp max of leaky logits
    float m = -__int_as_float(0x7F800000);
    for (int j = beg + lane; j < end; j += 32)
        m = fmaxf(m, leaky(g_asrc[g_srcs[j]] + adst));
    #pragma unroll
    for (int o = 16; o; o >>= 1) m = fmaxf(m, __shfl_xor_sync(0xFFFFFFFFu, m, o));

    // pass 2: warp sum of exp
    float s = 0.0f;
    for (int j = beg + lane; j < end; j += 32)
        s += __expf(leaky(g_asrc[g_srcs[j]] + adst) - m);
    #pragma unroll
    for (int o = 16; o; o >>= 1) s += __shfl_xor_sync(0xFFFFFFFFu, s, o);
    const float inv = 1.0f / (s + 1e-16f);

    // pass 3: sequential edge loop, coalesced float4 gather of this warp's slice
    const int fo = part * 32;
    float4 acc = make_float4(0.f, 0.f, 0.f, 0.f);
    for (int j = beg; j < end; j++) {
        int src = g_srcs[j];                 // warp-broadcast
        float alpha = __expf(leaky(g_asrc[src] + adst) - m) * inv;
        float4 v = reinterpret_cast<const float4*>(g_H + (size_t)src * C)[fo + lane];
        acc.x += alpha * v.x; acc.y += alpha * v.y;
        acc.z += alpha * v.z; acc.w += alpha * v.w;
    }

    float4 b0 = reinterpret_cast<const float4*>(bias)[fo + lane];
    acc.x += b0.x; acc.y += b0.y; acc.z += b0.z; acc.w += b0.w;
    if (RELU) {
        acc.x = fmaxf(acc.x, 0.f); acc.y = fmaxf(acc.y, 0.f);
        acc.z = fmaxf(acc.z, 0.f); acc.w = fmaxf(acc.w, 0.f);
    }
    reinterpret_cast<float4*>(out + (size_t)node * C)[fo + lane] = acc;
}

// ---------------- launch ----------------------------------------------------
extern "C" void kernel_launch(void* const* d_in, const int* in_sizes, int n_in,
                              void* d_out, int out_size) {
    const float* x        = (const float*)d_in[0];
    const int*   ei       = (const int*)d_in[1];   // int32 (JAX x64 disabled)
    const float* W1_src   = (const float*)d_in[2];
    const float* W1_dst   = (const float*)d_in[3];
    const float* att1_src = (const float*)d_in[4];
    const float* att1_dst = (const float*)d_in[5];
    const float* b1       = (const float*)d_in[6];
    const float* W2_src   = (const float*)d_in[7];
    const float* W2_dst   = (const float*)d_in[8];
    const float* att2_src = (const float*)d_in[9];
    const float* att2_dst = (const float*)d_in[10];
    const float* b2       = (const float*)d_in[11];
    float* out = (float*)d_out;

    static bool attr_done = false;
    if (!attr_done) {
        cudaFuncSetAttribute(wmma_gemm_kernel,
                             cudaFuncAttributeMaxDynamicSharedMemorySize, SM_BYTES);
        attr_done = true;
    }

    const int nodeBlocks  = (N_NODES + 255) / 256;
    const int edgeBlocks  = (N_EDGES + 255) / 256;
    const int warpNodeBlk = (N_NODES * 32 + 255) / 256;
    const int gemmRows    = (N_NODES + 127) / 128;   // 391

    // CSR build (shared by both layers)
    zero_deg_kernel<<<nodeBlocks, 256>>>();
    hist_kernel<<<edgeBlocks, 256>>>(ei);
    scan_kernel<<<1, 1024>>>();
    fill_kernel<<<edgeBlocks, 256>>>(ei);

    // ---------------- layer 1 (256 -> 256) ----------------
    compute_v_kernel<<<2, HID>>>(W1_src, att1_src, W1_dst, att1_dst, HID, HID);
    compute_a_kernel<<<warpNodeBlk, 256>>>(x, HID);
    convert_W_kernel<<<(256 * HID + 255) / 256, 256>>>(W1_src, HID);
    wmma_gemm_kernel<<<dim3(gemmRows, HID / 128), 256, SM_BYTES>>>(x, N_NODES, HID);
    agg_kernel<HID, true, 2><<<(N_NODES * 2 * 32 + 255) / 256, 256>>>(nullptr, b1);

    // ---------------- layer 2 (256 -> 128) ----------------
    compute_v_kernel<<<2, HID>>>(W2_src, att2_src, W2_dst, att2_dst, HID, OUTC);
    compute_a_kernel<<<warpNodeBlk, 256>>>(nullptr, HID);
    convert_W_kernel<<<(256 * OUTC + 255) / 256, 256>>>(W2_src, OUTC);
    wmma_gemm_kernel<<<dim3(gemmRows, OUTC / 128), 256, SM_BYTES>>>(nullptr, N_NODES, OUTC);
    agg_kernel<OUTC, false, 1><<<warpNodeBlk, 256>>>(out, b2);
}